// round 2
// baseline (speedup 1.0000x reference)
#include <cuda_runtime.h>
#include <cuda_bf16.h>
#include <math.h>

// ---------------- Problem constants ----------------
#define BB     2
#define LL     4096
#define DMODEL 1024
#define DSTATE 64
#define DCONV  4
#define DINNER 2048
#define DBCW   (2*DSTATE + DINNER)   // 2176
#define ROWS   (BB*LL)               // 8192
#define EPSV   1.1920929e-07f

// scan chunking
#define CHUNK  128
#define NCHUNK (LL/CHUNK)            // 32

// ---------------- Scratch (device globals; no allocs allowed) ----------------
__device__ __align__(128) float g_xz [ROWS * (2*DINNER)];  // [row][0:2048]=x_ssm, [2048:4096]=z
__device__ __align__(128) float g_xc [ROWS * DINNER];      // silu(conv(x_ssm))
__device__ __align__(128) float g_dbc[ROWS * DBCW];        // [row][0:64]=B, [64:128]=C, [128:2176]=dt_pre
__device__ __align__(128) float g_dt [ROWS * DINNER];      // softplus(dt)
__device__ __align__(128) float g_y  [ROWS * DINNER];      // scan output (+ D skip)
__device__ __align__(128) float g_yn [ROWS * DINNER];      // normed, gated
// chunk carries: layout [(b*NCHUNK + j)*DSTATE + s][d]
__device__ __align__(128) float g_E  [BB*NCHUNK*DSTATE*DINNER];
__device__ __align__(128) float g_P  [BB*NCHUNK*DSTATE*DINNER];
__device__ __align__(128) float g_hin[BB*NCHUNK*DSTATE*DINNER];

// ---------------- helpers ----------------
__device__ __forceinline__ float ex2f(float x) {
    float y; asm("ex2.approx.ftz.f32 %0, %1;" : "=f"(y) : "f"(x)); return y;
}
__device__ __forceinline__ float softplus_f(float x) {
    return x > 20.f ? x : log1pf(expf(x));
}
__device__ __forceinline__ float silu_f(float x) {
    return x / (1.f + expf(-x));
}

// ---------------- generic 128x128x16 fp32 GEMM core (double-buffered loads) --
// A: [.,K] row-major stride lda (already offset to block row)
// B: [K,.] row-major stride ldb (already offset to block col)
__device__ __forceinline__ void gemm_core(const float* __restrict__ A,
                                          const float* __restrict__ B,
                                          int K, int lda, int ldb,
                                          float (&acc)[8][8]) {
    __shared__ float As[16][128];
    __shared__ float Bs[16][128];
    const int tid   = threadIdx.x;
    const int arow  = tid >> 2;          // 0..63
    const int acol4 = (tid & 3) << 2;    // 0,4,8,12
    const int brow  = tid >> 5;          // 0..7
    const int bcol4 = (tid & 31) << 2;   // 0..124
    const int tx = tid & 15, ty = tid >> 4;

    // prologue: fetch tile 0 into registers
    float4 a0 = *(const float4*)&A[(size_t)arow        * lda + acol4];
    float4 a1 = *(const float4*)&A[(size_t)(arow + 64) * lda + acol4];
    float4 b0 = *(const float4*)&B[(size_t)brow       * ldb + bcol4];
    float4 b1 = *(const float4*)&B[(size_t)(brow + 8) * ldb + bcol4];

    for (int k0 = 0; k0 < K; k0 += 16) {
        // store staged tile to smem
        As[acol4 + 0][arow]      = a0.x;
        As[acol4 + 1][arow]      = a0.y;
        As[acol4 + 2][arow]      = a0.z;
        As[acol4 + 3][arow]      = a0.w;
        As[acol4 + 0][arow + 64] = a1.x;
        As[acol4 + 1][arow + 64] = a1.y;
        As[acol4 + 2][arow + 64] = a1.z;
        As[acol4 + 3][arow + 64] = a1.w;
        *(float4*)&Bs[brow    ][bcol4] = b0;
        *(float4*)&Bs[brow + 8][bcol4] = b1;
        __syncthreads();

        // prefetch next tile while computing this one
        const int kn = k0 + 16;
        if (kn < K) {
            a0 = *(const float4*)&A[(size_t)arow        * lda + kn + acol4];
            a1 = *(const float4*)&A[(size_t)(arow + 64) * lda + kn + acol4];
            b0 = *(const float4*)&B[(size_t)(kn + brow    ) * ldb + bcol4];
            b1 = *(const float4*)&B[(size_t)(kn + brow + 8) * ldb + bcol4];
        }

        #pragma unroll
        for (int k = 0; k < 16; k++) {
            float ra[8], rb[8];
            #pragma unroll
            for (int i = 0; i < 8; i++) ra[i] = As[k][ty * 8 + i];
            #pragma unroll
            for (int j = 0; j < 8; j++) rb[j] = Bs[k][tx * 8 + j];
            #pragma unroll
            for (int i = 0; i < 8; i++)
                #pragma unroll
                for (int j = 0; j < 8; j++)
                    acc[i][j] = fmaf(ra[i], rb[j], acc[i][j]);
        }
        __syncthreads();
    }
}

// ---------------- GEMM1: xz = x @ W_in  (8192 x 4096 x K=1024) ----------------
__global__ __launch_bounds__(256) void gemm1_kernel(const float* __restrict__ x,
                                                    const float* __restrict__ W_in) {
    float acc[8][8] = {};
    const float* A = x    + (size_t)blockIdx.y * 128 * DMODEL;
    const float* B = W_in + (size_t)blockIdx.x * 128;
    gemm_core(A, B, DMODEL, DMODEL, 2*DINNER, acc);
    const int row0 = blockIdx.y * 128 + (threadIdx.x >> 4) * 8;
    const int col0 = blockIdx.x * 128 + (threadIdx.x & 15) * 8;
    #pragma unroll
    for (int i = 0; i < 8; i++) {
        float4 v0 = make_float4(acc[i][0], acc[i][1], acc[i][2], acc[i][3]);
        float4 v1 = make_float4(acc[i][4], acc[i][5], acc[i][6], acc[i][7]);
        *(float4*)&g_xz[(size_t)(row0 + i) * (2*DINNER) + col0]     = v0;
        *(float4*)&g_xz[(size_t)(row0 + i) * (2*DINNER) + col0 + 4] = v1;
    }
}

// ---------------- causal depthwise conv(4) + bias + SiLU ----------------
__global__ __launch_bounds__(256) void conv_silu_kernel(const float* __restrict__ cw,
                                                        const float* __restrict__ cb) {
    int idx = blockIdx.x * 256 + threadIdx.x;        // (b*L+t)*DINNER + d
    int d   = idx & (DINNER - 1);
    int row = idx >> 11;                              // b*L + t
    int t   = row & (LL - 1);
    float acc = cb[d];
    #pragma unroll
    for (int k = 0; k < DCONV; k++) {
        int tt = t - (DCONV - 1) + k;
        if (tt >= 0)
            acc = fmaf(g_xz[(size_t)(row - (DCONV - 1) + k) * (2*DINNER) + d], cw[d * DCONV + k], acc);
    }
    g_xc[idx] = silu_f(acc);
}

// ---------------- GEMM2: dbc = xc @ W_x (8192 x 2176 x K=2048) ----------------
__global__ __launch_bounds__(256) void gemm2_kernel(const float* __restrict__ W_x) {
    float acc[8][8] = {};
    const float* A = g_xc + (size_t)blockIdx.y * 128 * DINNER;
    const float* B = W_x  + (size_t)blockIdx.x * 128;
    gemm_core(A, B, DINNER, DINNER, DBCW, acc);
    const int row0 = blockIdx.y * 128 + (threadIdx.x >> 4) * 8;
    const int col0 = blockIdx.x * 128 + (threadIdx.x & 15) * 8;
    #pragma unroll
    for (int i = 0; i < 8; i++) {
        float4 v0 = make_float4(acc[i][0], acc[i][1], acc[i][2], acc[i][3]);
        float4 v1 = make_float4(acc[i][4], acc[i][5], acc[i][6], acc[i][7]);
        *(float4*)&g_dbc[(size_t)(row0 + i) * DBCW + col0]     = v0;
        *(float4*)&g_dbc[(size_t)(row0 + i) * DBCW + col0 + 4] = v1;
    }
}

// ---------------- GEMM3: dt = softplus(dt_pre @ W_dt + b_dt) ----------------
__global__ __launch_bounds__(256) void gemm3_kernel(const float* __restrict__ W_dt,
                                                    const float* __restrict__ b_dt) {
    float acc[8][8] = {};
    const float* A = g_dbc + (size_t)blockIdx.y * 128 * DBCW + 2*DSTATE;  // dt_pre slice
    const float* B = W_dt  + (size_t)blockIdx.x * 128;
    gemm_core(A, B, DINNER, DBCW, DINNER, acc);
    const int row0 = blockIdx.y * 128 + (threadIdx.x >> 4) * 8;
    const int col0 = blockIdx.x * 128 + (threadIdx.x & 15) * 8;
    #pragma unroll
    for (int i = 0; i < 8; i++) {
        #pragma unroll
        for (int j = 0; j < 8; j++) {
            int r = row0 + i, c = col0 + j;
            g_dt[(size_t)r * DINNER + c] = softplus_f(acc[i][j] + b_dt[c]);
        }
    }
}

// ---------------- Scan phase 1: per-chunk local scan -> E, P ----------------
// block = 256 threads = 128 d-channels x 2 halves(32 states each)
// grid  = BB * NCHUNK * (DINNER/128) = 2*32*16 = 1024
__global__ __launch_bounds__(256) void scan_phase1(const float* __restrict__ A_log) {
    const int blk   = blockIdx.x;
    const int dgrp  = blk & 15;
    const int chunk = (blk >> 4) & (NCHUNK - 1);
    const int b     = blk >> 9;
    const int tid   = threadIdx.x;
    const int dloc  = tid >> 1;
    const int half  = tid & 1;
    const int d     = dgrp * 128 + dloc;
    const int s0    = half * 32;

    float a2[32], h[32], p[32];
    #pragma unroll
    for (int i = 0; i < 32; i++) {
        a2[i] = -expf(A_log[d * DSTATE + s0 + i]) * 1.44269504088896340736f; // A*log2(e)
        h[i]  = 0.f;
        p[i]  = 1.f;
    }
    __shared__ float sBC[2][128];
    const int rowbase = b * LL + chunk * CHUNK;
    for (int t = 0; t < CHUNK; t++) {
        const int row = rowbase + t;
        if (tid < 128) sBC[t & 1][tid] = g_dbc[(size_t)row * DBCW + tid];
        __syncthreads();
        const float dtv = g_dt[(size_t)row * DINNER + d];
        const float uv  = dtv * g_xc[(size_t)row * DINNER + d];
        const float* Bv = &sBC[t & 1][s0];
        #pragma unroll
        for (int i = 0; i < 32; i++) {
            float dA = ex2f(dtv * a2[i]);
            p[i] *= dA;
            h[i] = fmaf(dA, h[i], uv * Bv[i]);
        }
    }
    const int base = ((b * NCHUNK + chunk) * DSTATE + s0) * DINNER + d;
    #pragma unroll
    for (int i = 0; i < 32; i++) {
        g_E[base + i * DINNER] = h[i];
        g_P[base + i * DINNER] = p[i];
    }
}

// ---------------- Scan phase 2: sequential combine across chunks ----------------
// one thread per (b, s, d): 2*64*2048 = 262144 threads
__global__ __launch_bounds__(256) void scan_combine() {
    const int idx = blockIdx.x * 256 + threadIdx.x;   // (b*64+s)*2048 + d
    const int d   = idx & (DINNER - 1);
    const int bs  = idx >> 11;
    const int b   = bs >> 6;
    const int s   = bs & 63;
    float h = 0.f;
    for (int j = 0; j < NCHUNK; j++) {
        const int o = ((b * NCHUNK + j) * DSTATE + s) * DINNER + d;
        g_hin[o] = h;
        h = fmaf(g_P[o], h, g_E[o]);
    }
}

// ---------------- Scan phase 3: full recurrence with carry-in, emit y ----------------
__global__ __launch_bounds__(256) void scan_phase3(const float* __restrict__ A_log,
                                                   const float* __restrict__ D_param) {
    const int blk   = blockIdx.x;
    const int dgrp  = blk & 15;
    const int chunk = (blk >> 4) & (NCHUNK - 1);
    const int b     = blk >> 9;
    const int tid   = threadIdx.x;
    const int dloc  = tid >> 1;
    const int half  = tid & 1;
    const int d     = dgrp * 128 + dloc;
    const int s0    = half * 32;

    float a2[32], h[32];
    const int hbase = ((b * NCHUNK + chunk) * DSTATE + s0) * DINNER + d;
    #pragma unroll
    for (int i = 0; i < 32; i++) {
        a2[i] = -expf(A_log[d * DSTATE + s0 + i]) * 1.44269504088896340736f;
        h[i]  = g_hin[hbase + i * DINNER];
    }
    const float Dv = D_param[d];
    __shared__ float sBC[2][128];
    const int rowbase = b * LL + chunk * CHUNK;
    for (int t = 0; t < CHUNK; t++) {
        const int row = rowbase + t;
        if (tid < 128) sBC[t & 1][tid] = g_dbc[(size_t)row * DBCW + tid];
        __syncthreads();
        const float dtv = g_dt[(size_t)row * DINNER + d];
        const float xcv = g_xc[(size_t)row * DINNER + d];
        const float uv  = dtv * xcv;
        const float* Bv = &sBC[t & 1][s0];
        const float* Cv = &sBC[t & 1][64 + s0];
        float yacc = 0.f;
        #pragma unroll
        for (int i = 0; i < 32; i++) {
            float dA = ex2f(dtv * a2[i]);
            h[i] = fmaf(dA, h[i], uv * Bv[i]);
            yacc = fmaf(h[i], Cv[i], yacc);
        }
        yacc += __shfl_xor_sync(0xffffffffu, yacc, 1);
        if (half == 0) {
            const size_t o = (size_t)row * DINNER + d;
            g_y[o] = yacc + Dv * xcv;
        }
    }
}

// ---------------- RMSNorm + silu(z) gate ----------------
__global__ __launch_bounds__(256) void norm_kernel(const float* __restrict__ norm_w) {
    const int row  = blockIdx.x;
    const int tid  = threadIdx.x;
    const size_t base = (size_t)row * DINNER;
    float ss = 0.f;
    for (int i = tid; i < DINNER; i += 256) {
        float v = g_y[base + i];
        ss = fmaf(v, v, ss);
    }
    #pragma unroll
    for (int o = 16; o; o >>= 1) ss += __shfl_xor_sync(0xffffffffu, ss, o);
    __shared__ float red[8];
    __shared__ float s_inv;
    if ((tid & 31) == 0) red[tid >> 5] = ss;
    __syncthreads();
    if (tid == 0) {
        float t = 0.f;
        #pragma unroll
        for (int i = 0; i < 8; i++) t += red[i];
        s_inv = rsqrtf(t / (float)DINNER + EPSV);
    }
    __syncthreads();
    const float inv = s_inv;
    for (int i = tid; i < DINNER; i += 256) {
        float v  = g_y[base + i] * inv * norm_w[i];
        float zv = g_xz[(size_t)row * (2*DINNER) + DINNER + i];
        g_yn[base + i] = v * silu_f(zv);
    }
}

// ---------------- GEMM4: out = yn @ W_out (8192 x 1024 x K=2048) ----------------
__global__ __launch_bounds__(256) void gemm4_kernel(const float* __restrict__ W_out,
                                                    float* __restrict__ out) {
    float acc[8][8] = {};
    const float* A = g_yn  + (size_t)blockIdx.y * 128 * DINNER;
    const float* B = W_out + (size_t)blockIdx.x * 128;
    gemm_core(A, B, DINNER, DINNER, DMODEL, acc);
    const int row0 = blockIdx.y * 128 + (threadIdx.x >> 4) * 8;
    const int col0 = blockIdx.x * 128 + (threadIdx.x & 15) * 8;
    #pragma unroll
    for (int i = 0; i < 8; i++) {
        float4 v0 = make_float4(acc[i][0], acc[i][1], acc[i][2], acc[i][3]);
        float4 v1 = make_float4(acc[i][4], acc[i][5], acc[i][6], acc[i][7]);
        *(float4*)&out[(size_t)(row0 + i) * DMODEL + col0]     = v0;
        *(float4*)&out[(size_t)(row0 + i) * DMODEL + col0 + 4] = v1;
    }
}

// ---------------- launch ----------------
extern "C" void kernel_launch(void* const* d_in, const int* in_sizes, int n_in,
                              void* d_out, int out_size) {
    const float* x      = (const float*)d_in[0];
    const float* W_in   = (const float*)d_in[1];
    const float* conv_w = (const float*)d_in[2];
    const float* conv_b = (const float*)d_in[3];
    const float* W_x    = (const float*)d_in[4];
    const float* W_dt   = (const float*)d_in[5];
    const float* b_dt   = (const float*)d_in[6];
    const float* A_log  = (const float*)d_in[7];
    const float* D_par  = (const float*)d_in[8];
    const float* W_out  = (const float*)d_in[9];
    const float* norm_w = (const float*)d_in[10];
    float* out = (float*)d_out;

    gemm1_kernel<<<dim3((2*DINNER)/128, ROWS/128), 256>>>(x, W_in);
    conv_silu_kernel<<<(ROWS * DINNER) / 256, 256>>>(conv_w, conv_b);
    gemm2_kernel<<<dim3(DBCW/128, ROWS/128), 256>>>(W_x);
    gemm3_kernel<<<dim3(DINNER/128, ROWS/128), 256>>>(W_dt, b_dt);
    scan_phase1<<<BB * NCHUNK * (DINNER/128), 256>>>(A_log);
    scan_combine<<<(BB * DSTATE * DINNER) / 256, 256>>>();
    scan_phase3<<<BB * NCHUNK * (DINNER/128), 256>>>(A_log, D_par);
    norm_kernel<<<ROWS, 256>>>(norm_w);
    gemm4_kernel<<<dim3(DMODEL/128, ROWS/128), 256>>>(W_out, out);
}

// round 3
// speedup vs baseline: 1.7665x; 1.7665x over previous
#include <cuda_runtime.h>
#include <cuda_bf16.h>
#include <math.h>
#include <stdint.h>

// ---------------- Problem constants ----------------
#define BB     2
#define LL     4096
#define DMODEL 1024
#define DSTATE 64
#define DCONV  4
#define DINNER 2048
#define DBCW   (2*DSTATE + DINNER)   // 2176
#define ROWS   (BB*LL)               // 8192
#define EPSV   1.1920929e-07f

// scan chunking
#define CHUNK  128
#define NCHUNK (LL/CHUNK)            // 32

// ---------------- Scratch (device globals; no allocs allowed) ----------------
__device__ __align__(128) float g_xz [ROWS * (2*DINNER)];  // [row][0:2048]=x_ssm, [2048:4096]=z
__device__ __align__(128) float g_xc [ROWS * DINNER];      // silu(conv(x_ssm))
__device__ __align__(128) float g_dbc[ROWS * DBCW];        // [row][0:64]=B, [64:128]=C, [128:2176]=dt_pre
__device__ __align__(128) float g_dt [ROWS * DINNER];      // softplus(dt)
__device__ __align__(128) float g_y  [ROWS * DINNER];      // scan output (+ D skip)
__device__ __align__(128) float g_yn [ROWS * DINNER];      // normed, gated
// chunk carries: layout [(b*NCHUNK + j)*DSTATE + s][d]
__device__ __align__(128) float g_E  [BB*NCHUNK*DSTATE*DINNER];
__device__ __align__(128) float g_P  [BB*NCHUNK*DSTATE*DINNER];
__device__ __align__(128) float g_hin[BB*NCHUNK*DSTATE*DINNER];

// ---------------- helpers ----------------
__device__ __forceinline__ float ex2f(float x) {
    float y; asm("ex2.approx.ftz.f32 %0, %1;" : "=f"(y) : "f"(x)); return y;
}
__device__ __forceinline__ float softplus_f(float x) {
    return x > 20.f ? x : log1pf(expf(x));
}
__device__ __forceinline__ float silu_f(float x) {
    return x / (1.f + expf(-x));
}

// pack two fp32 -> bf16x2 (lo half = first arg)
__device__ __forceinline__ uint32_t pack_bf2(float lo, float hi) {
    uint32_t r;
    asm("cvt.rn.bf16x2.f32 %0, %1, %2;" : "=r"(r) : "f"(hi), "f"(lo));
    return r;
}

__device__ __forceinline__ void mma_bf16(float (&d)[4], const uint32_t* a, const uint32_t* b) {
    asm volatile(
        "mma.sync.aligned.m16n8k16.row.col.f32.bf16.bf16.f32 "
        "{%0,%1,%2,%3}, {%4,%5,%6,%7}, {%8,%9}, {%0,%1,%2,%3};"
        : "+f"(d[0]), "+f"(d[1]), "+f"(d[2]), "+f"(d[3])
        : "r"(a[0]), "r"(a[1]), "r"(a[2]), "r"(a[3]),
          "r"(b[0]), "r"(b[1]));
}

// ---------------- bf16x3 tensor-core GEMM core ----------------
// Tile: BM=128, BN=128, BK=32. 256 threads / 8 warps, warp tile 64x32.
// smem holds pre-split, fragment-permuted bf16x2 data:
//   sAhi/sAlo: [mtile(8)][kstep(2)][lane(32)] x uint4      (2048 u32 each)
//   sBhi/sBlo: [ntile(16)][kstep(2)][lane(33 padded)] x uint2 (2112 u32 each)
#define GA_IDX(mtile,ks,lane) ((((mtile)*2 + (ks))*32 + (lane))*4)
#define GB_IDX(ntile,ks,lane) ((((ntile)*2 + (ks))*33 + (lane))*2)

__device__ __forceinline__ void gemm_core_tc(const float* __restrict__ A,
                                             const float* __restrict__ B,
                                             int K, int lda, int ldb,
                                             float (&acc)[4][4][4]) {
    __shared__ uint32_t sAhi[2048], sAlo[2048];
    __shared__ uint32_t sBhi[2112], sBlo[2112];

    const int t    = threadIdx.x;
    const int lane = t & 31;
    const int wid  = t >> 5;
    const int mt0  = (wid & 1) * 4;   // mtile base (of 8)
    const int nt0  = (wid >> 1) * 4;  // ntile base (of 16)

    // ---- loader thread mapping ----
    // A: thread covers row am (0..127), k range [aks*16, +16)
    const int am   = t >> 1;
    const int aks  = t & 1;
    const int amt  = am >> 4;
    const int ar   = am & 15;
    const int ag   = ar & 7;
    const int aup  = ar >> 3;
    const int abase = GA_IDX(amt, aks, ag * 4);
    // B: thread covers rows bk,bk+1 (k), cols [bnt*8, +8)
    const int bk   = (t >> 4) * 2;
    const int bnt  = t & 15;
    const int bks  = bk >> 4;
    const int bkk  = bk & 15;
    const int bti  = (bkk >> 1) & 3;
    const int b01  = bkk >> 3;

    float av[16], bv0[8], bv1[8];

    // prologue: stage tile 0
    {
        const float* ap = A + (size_t)am * lda + aks * 16;
        *(float4*)&av[0]  = *(const float4*)&ap[0];
        *(float4*)&av[4]  = *(const float4*)&ap[4];
        *(float4*)&av[8]  = *(const float4*)&ap[8];
        *(float4*)&av[12] = *(const float4*)&ap[12];
        const float* bp0 = B + (size_t)bk * ldb + bnt * 8;
        const float* bp1 = bp0 + ldb;
        *(float4*)&bv0[0] = *(const float4*)&bp0[0];
        *(float4*)&bv0[4] = *(const float4*)&bp0[4];
        *(float4*)&bv1[0] = *(const float4*)&bp1[0];
        *(float4*)&bv1[4] = *(const float4*)&bp1[4];
    }

    for (int k0 = 0; k0 < K; k0 += 32) {
        // ---- split + store staged tile to smem ----
        #pragma unroll
        for (int j = 0; j < 8; j++) {
            float a0 = av[2*j], a1 = av[2*j+1];
            uint32_t h = pack_bf2(a0, a1);
            float l0 = a0 - __uint_as_float(h << 16);
            float l1 = a1 - __uint_as_float(h & 0xFFFF0000u);
            uint32_t l = pack_bf2(l0, l1);
            int idx = abase + (j & 3) * 4 + (aup + 2 * (j >> 2));
            sAhi[idx] = h; sAlo[idx] = l;
        }
        #pragma unroll
        for (int j = 0; j < 8; j++) {
            float a0 = bv0[j], a1 = bv1[j];
            uint32_t h = pack_bf2(a0, a1);
            float l0 = a0 - __uint_as_float(h << 16);
            float l1 = a1 - __uint_as_float(h & 0xFFFF0000u);
            uint32_t l = pack_bf2(l0, l1);
            int idx = GB_IDX(bnt, bks, j * 4 + bti) + b01;
            sBhi[idx] = h; sBlo[idx] = l;
        }
        __syncthreads();

        // ---- prefetch next tile ----
        const int kn = k0 + 32;
        if (kn < K) {
            const float* ap = A + (size_t)am * lda + kn + aks * 16;
            *(float4*)&av[0]  = *(const float4*)&ap[0];
            *(float4*)&av[4]  = *(const float4*)&ap[4];
            *(float4*)&av[8]  = *(const float4*)&ap[8];
            *(float4*)&av[12] = *(const float4*)&ap[12];
            const float* bp0 = B + (size_t)(kn + bk) * ldb + bnt * 8;
            const float* bp1 = bp0 + ldb;
            *(float4*)&bv0[0] = *(const float4*)&bp0[0];
            *(float4*)&bv0[4] = *(const float4*)&bp0[4];
            *(float4*)&bv1[0] = *(const float4*)&bp1[0];
            *(float4*)&bv1[4] = *(const float4*)&bp1[4];
        }

        // ---- compute: 2 ksteps of m16n8k16 ----
        #pragma unroll
        for (int ks = 0; ks < 2; ks++) {
            uint32_t bh[4][2], bl[4][2];
            #pragma unroll
            for (int nt = 0; nt < 4; nt++) {
                int bi = GB_IDX(nt0 + nt, ks, lane);
                *(uint2*)bh[nt] = *(const uint2*)&sBhi[bi];
                *(uint2*)bl[nt] = *(const uint2*)&sBlo[bi];
            }
            #pragma unroll
            for (int mt = 0; mt < 4; mt++) {
                int ai = GA_IDX(mt0 + mt, ks, lane);
                uint32_t ah[4], al[4];
                *(uint4*)ah = *(const uint4*)&sAhi[ai];
                *(uint4*)al = *(const uint4*)&sAlo[ai];
                #pragma unroll
                for (int nt = 0; nt < 4; nt++) {
                    mma_bf16(acc[mt][nt], ah, bh[nt]);
                    mma_bf16(acc[mt][nt], al, bh[nt]);
                    mma_bf16(acc[mt][nt], ah, bl[nt]);
                }
            }
        }
        __syncthreads();
    }
}

// epilogue coordinates: for (mt, nt): rows m0+mt*16+(lane>>2) and +8,
// cols n0+nt*8+(lane&3)*2 (+1)
#define EPI_SETUP() \
    const int lane = threadIdx.x & 31; \
    const int wid  = threadIdx.x >> 5; \
    const int mrow = blockIdx.y * 128 + (wid & 1) * 64 + (lane >> 2); \
    const int ncol = blockIdx.x * 128 + (wid >> 1) * 32 + (lane & 3) * 2;

// ---------------- GEMM1: xz = x @ W_in  (8192 x 4096 x K=1024) ----------------
__global__ __launch_bounds__(256, 1) void gemm1_kernel(const float* __restrict__ x,
                                                       const float* __restrict__ W_in) {
    float acc[4][4][4] = {};
    const float* A = x    + (size_t)blockIdx.y * 128 * DMODEL;
    const float* B = W_in + (size_t)blockIdx.x * 128;
    gemm_core_tc(A, B, DMODEL, DMODEL, 2*DINNER, acc);
    EPI_SETUP();
    #pragma unroll
    for (int mt = 0; mt < 4; mt++)
        #pragma unroll
        for (int nt = 0; nt < 4; nt++) {
            int r = mrow + mt * 16, c = ncol + nt * 8;
            *(float2*)&g_xz[(size_t)r * (2*DINNER) + c]       = make_float2(acc[mt][nt][0], acc[mt][nt][1]);
            *(float2*)&g_xz[(size_t)(r + 8) * (2*DINNER) + c] = make_float2(acc[mt][nt][2], acc[mt][nt][3]);
        }
}

// ---------------- causal depthwise conv(4) + bias + SiLU ----------------
__global__ __launch_bounds__(256) void conv_silu_kernel(const float* __restrict__ cw,
                                                        const float* __restrict__ cb) {
    int idx = blockIdx.x * 256 + threadIdx.x;        // (b*L+t)*DINNER + d
    int d   = idx & (DINNER - 1);
    int row = idx >> 11;                              // b*L + t
    int t   = row & (LL - 1);
    float acc = cb[d];
    #pragma unroll
    for (int k = 0; k < DCONV; k++) {
        int tt = t - (DCONV - 1) + k;
        if (tt >= 0)
            acc = fmaf(g_xz[(size_t)(row - (DCONV - 1) + k) * (2*DINNER) + d], cw[d * DCONV + k], acc);
    }
    g_xc[idx] = silu_f(acc);
}

// ---------------- GEMM2: dbc = xc @ W_x (8192 x 2176 x K=2048) ----------------
__global__ __launch_bounds__(256, 1) void gemm2_kernel(const float* __restrict__ W_x) {
    float acc[4][4][4] = {};
    const float* A = g_xc + (size_t)blockIdx.y * 128 * DINNER;
    const float* B = W_x  + (size_t)blockIdx.x * 128;
    gemm_core_tc(A, B, DINNER, DINNER, DBCW, acc);
    EPI_SETUP();
    #pragma unroll
    for (int mt = 0; mt < 4; mt++)
        #pragma unroll
        for (int nt = 0; nt < 4; nt++) {
            int r = mrow + mt * 16, c = ncol + nt * 8;
            *(float2*)&g_dbc[(size_t)r * DBCW + c]       = make_float2(acc[mt][nt][0], acc[mt][nt][1]);
            *(float2*)&g_dbc[(size_t)(r + 8) * DBCW + c] = make_float2(acc[mt][nt][2], acc[mt][nt][3]);
        }
}

// ---------------- GEMM3: dt = softplus(dt_pre @ W_dt + b_dt) ----------------
__global__ __launch_bounds__(256, 1) void gemm3_kernel(const float* __restrict__ W_dt,
                                                       const float* __restrict__ b_dt) {
    float acc[4][4][4] = {};
    const float* A = g_dbc + (size_t)blockIdx.y * 128 * DBCW + 2*DSTATE;  // dt_pre slice
    const float* B = W_dt  + (size_t)blockIdx.x * 128;
    gemm_core_tc(A, B, DINNER, DBCW, DINNER, acc);
    EPI_SETUP();
    #pragma unroll
    for (int mt = 0; mt < 4; mt++)
        #pragma unroll
        for (int nt = 0; nt < 4; nt++) {
            int r = mrow + mt * 16, c = ncol + nt * 8;
            float b0 = b_dt[c], b1 = b_dt[c + 1];
            g_dt[(size_t)r * DINNER + c]           = softplus_f(acc[mt][nt][0] + b0);
            g_dt[(size_t)r * DINNER + c + 1]       = softplus_f(acc[mt][nt][1] + b1);
            g_dt[(size_t)(r + 8) * DINNER + c]     = softplus_f(acc[mt][nt][2] + b0);
            g_dt[(size_t)(r + 8) * DINNER + c + 1] = softplus_f(acc[mt][nt][3] + b1);
        }
}

// ---------------- Scan phase 1: per-chunk local scan -> E, P ----------------
__global__ __launch_bounds__(256) void scan_phase1(const float* __restrict__ A_log) {
    const int blk   = blockIdx.x;
    const int dgrp  = blk & 15;
    const int chunk = (blk >> 4) & (NCHUNK - 1);
    const int b     = blk >> 9;
    const int tid   = threadIdx.x;
    const int dloc  = tid >> 1;
    const int half  = tid & 1;
    const int d     = dgrp * 128 + dloc;
    const int s0    = half * 32;

    float a2[32], h[32], p[32];
    #pragma unroll
    for (int i = 0; i < 32; i++) {
        a2[i] = -expf(A_log[d * DSTATE + s0 + i]) * 1.44269504088896340736f; // A*log2(e)
        h[i]  = 0.f;
        p[i]  = 1.f;
    }
    __shared__ float sBC[2][128];
    const int rowbase = b * LL + chunk * CHUNK;
    for (int t = 0; t < CHUNK; t++) {
        const int row = rowbase + t;
        if (tid < 128) sBC[t & 1][tid] = g_dbc[(size_t)row * DBCW + tid];
        __syncthreads();
        const float dtv = g_dt[(size_t)row * DINNER + d];
        const float uv  = dtv * g_xc[(size_t)row * DINNER + d];
        const float* Bv = &sBC[t & 1][s0];
        #pragma unroll
        for (int i = 0; i < 32; i++) {
            float dA = ex2f(dtv * a2[i]);
            p[i] *= dA;
            h[i] = fmaf(dA, h[i], uv * Bv[i]);
        }
    }
    const int base = ((b * NCHUNK + chunk) * DSTATE + s0) * DINNER + d;
    #pragma unroll
    for (int i = 0; i < 32; i++) {
        g_E[base + i * DINNER] = h[i];
        g_P[base + i * DINNER] = p[i];
    }
}

// ---------------- Scan phase 2: sequential combine across chunks ----------------
__global__ __launch_bounds__(256) void scan_combine() {
    const int idx = blockIdx.x * 256 + threadIdx.x;   // (b*64+s)*2048 + d
    const int d   = idx & (DINNER - 1);
    const int bs  = idx >> 11;
    const int b   = bs >> 6;
    const int s   = bs & 63;
    float h = 0.f;
    for (int j = 0; j < NCHUNK; j++) {
        const int o = ((b * NCHUNK + j) * DSTATE + s) * DINNER + d;
        g_hin[o] = h;
        h = fmaf(g_P[o], h, g_E[o]);
    }
}

// ---------------- Scan phase 3: full recurrence with carry-in, emit y ----------------
__global__ __launch_bounds__(256) void scan_phase3(const float* __restrict__ A_log,
                                                   const float* __restrict__ D_param) {
    const int blk   = blockIdx.x;
    const int dgrp  = blk & 15;
    const int chunk = (blk >> 4) & (NCHUNK - 1);
    const int b     = blk >> 9;
    const int tid   = threadIdx.x;
    const int dloc  = tid >> 1;
    const int half  = tid & 1;
    const int d     = dgrp * 128 + dloc;
    const int s0    = half * 32;

    float a2[32], h[32];
    const int hbase = ((b * NCHUNK + chunk) * DSTATE + s0) * DINNER + d;
    #pragma unroll
    for (int i = 0; i < 32; i++) {
        a2[i] = -expf(A_log[d * DSTATE + s0 + i]) * 1.44269504088896340736f;
        h[i]  = g_hin[hbase + i * DINNER];
    }
    const float Dv = D_param[d];
    __shared__ float sBC[2][128];
    const int rowbase = b * LL + chunk * CHUNK;
    for (int t = 0; t < CHUNK; t++) {
        const int row = rowbase + t;
        if (tid < 128) sBC[t & 1][tid] = g_dbc[(size_t)row * DBCW + tid];
        __syncthreads();
        const float dtv = g_dt[(size_t)row * DINNER + d];
        const float xcv = g_xc[(size_t)row * DINNER + d];
        const float uv  = dtv * xcv;
        const float* Bv = &sBC[t & 1][s0];
        const float* Cv = &sBC[t & 1][64 + s0];
        float yacc = 0.f;
        #pragma unroll
        for (int i = 0; i < 32; i++) {
            float dA = ex2f(dtv * a2[i]);
            h[i] = fmaf(dA, h[i], uv * Bv[i]);
            yacc = fmaf(h[i], Cv[i], yacc);
        }
        yacc += __shfl_xor_sync(0xffffffffu, yacc, 1);
        if (half == 0) {
            const size_t o = (size_t)row * DINNER + d;
            g_y[o] = yacc + Dv * xcv;
        }
    }
}

// ---------------- RMSNorm + silu(z) gate ----------------
__global__ __launch_bounds__(256) void norm_kernel(const float* __restrict__ norm_w) {
    const int row  = blockIdx.x;
    const int tid  = threadIdx.x;
    const size_t base = (size_t)row * DINNER;
    float ss = 0.f;
    for (int i = tid; i < DINNER; i += 256) {
        float v = g_y[base + i];
        ss = fmaf(v, v, ss);
    }
    #pragma unroll
    for (int o = 16; o; o >>= 1) ss += __shfl_xor_sync(0xffffffffu, ss, o);
    __shared__ float red[8];
    __shared__ float s_inv;
    if ((tid & 31) == 0) red[tid >> 5] = ss;
    __syncthreads();
    if (tid == 0) {
        float t = 0.f;
        #pragma unroll
        for (int i = 0; i < 8; i++) t += red[i];
        s_inv = rsqrtf(t / (float)DINNER + EPSV);
    }
    __syncthreads();
    const float inv = s_inv;
    for (int i = tid; i < DINNER; i += 256) {
        float v  = g_y[base + i] * inv * norm_w[i];
        float zv = g_xz[(size_t)row * (2*DINNER) + DINNER + i];
        g_yn[base + i] = v * silu_f(zv);
    }
}

// ---------------- GEMM4: out = yn @ W_out (8192 x 1024 x K=2048) ----------------
__global__ __launch_bounds__(256, 1) void gemm4_kernel(const float* __restrict__ W_out,
                                                       float* __restrict__ out) {
    float acc[4][4][4] = {};
    const float* A = g_yn  + (size_t)blockIdx.y * 128 * DINNER;
    const float* B = W_out + (size_t)blockIdx.x * 128;
    gemm_core_tc(A, B, DINNER, DINNER, DMODEL, acc);
    EPI_SETUP();
    #pragma unroll
    for (int mt = 0; mt < 4; mt++)
        #pragma unroll
        for (int nt = 0; nt < 4; nt++) {
            int r = mrow + mt * 16, c = ncol + nt * 8;
            *(float2*)&out[(size_t)r * DMODEL + c]       = make_float2(acc[mt][nt][0], acc[mt][nt][1]);
            *(float2*)&out[(size_t)(r + 8) * DMODEL + c] = make_float2(acc[mt][nt][2], acc[mt][nt][3]);
        }
}

// ---------------- launch ----------------
extern "C" void kernel_launch(void* const* d_in, const int* in_sizes, int n_in,
                              void* d_out, int out_size) {
    const float* x      = (const float*)d_in[0];
    const float* W_in   = (const float*)d_in[1];
    const float* conv_w = (const float*)d_in[2];
    const float* conv_b = (const float*)d_in[3];
    const float* W_x    = (const float*)d_in[4];
    const float* W_dt   = (const float*)d_in[5];
    const float* b_dt   = (const float*)d_in[6];
    const float* A_log  = (const float*)d_in[7];
    const float* D_par  = (const float*)d_in[8];
    const float* W_out  = (const float*)d_in[9];
    const float* norm_w = (const float*)d_in[10];
    float* out = (float*)d_out;

    gemm1_kernel<<<dim3((2*DINNER)/128, ROWS/128), 256>>>(x, W_in);
    conv_silu_kernel<<<(ROWS * DINNER) / 256, 256>>>(conv_w, conv_b);
    gemm2_kernel<<<dim3(DBCW/128, ROWS/128), 256>>>(W_x);
    gemm3_kernel<<<dim3(DINNER/128, ROWS/128), 256>>>(W_dt, b_dt);
    scan_phase1<<<BB * NCHUNK * (DINNER/128), 256>>>(A_log);
    scan_combine<<<(BB * DSTATE * DINNER) / 256, 256>>>();
    scan_phase3<<<BB * NCHUNK * (DINNER/128), 256>>>(A_log, D_par);
    norm_kernel<<<ROWS, 256>>>(norm_w);
    gemm4_kernel<<<dim3(DMODEL/128, ROWS/128), 256>>>(W_out, out);
}